// round 2
// baseline (speedup 1.0000x reference)
#include <cuda_runtime.h>
#include <cuda_fp16.h>
#include <cstdint>

// Problem: out[32,14336] = (x * scales) @ W^T
//   x:      [32, 4096]  f32
//   W:      [14336, 4096] int32 (values in [-127,127])
//   scales: [4096] f32
//   out:    [32, 14336] f32
//
// Strategy: HBM-bound (235MB weight stream). Use mma.sync m16n8k16 fp16 so
// compute (3.76 GFLOP) is fully hidden under the weight stream.

#define TOKENS 32
#define IN_F   4096
#define OUT_F  14336
#define NUM_KB (IN_F / 16)      // 256 k16-blocks

// A-fragments of xs=x*scales in fp16, fragment-major:
// index ((kb*2 + mi)*32 + lane) -> uint4 (4 regs = 8 fp16 = one m16k16 A frag slice)
__device__ uint4 g_xsfrag[NUM_KB * 2 * 32];

// ---------------------------------------------------------------------------
// Prep: build fragment-major fp16 xs. One warp per (kb, mi). 512 warps total.
// ---------------------------------------------------------------------------
__global__ __launch_bounds__(256) void prep_xs_kernel(
    const float* __restrict__ x, const float* __restrict__ scales)
{
    int wg   = blockIdx.x * (blockDim.x >> 5) + (threadIdx.x >> 5); // 0..511
    int lane = threadIdx.x & 31;
    int kb = wg >> 1;
    int mi = wg & 1;

    int q = lane & 3;        // k-quad
    int g = lane >> 2;       // group row
    int r0 = mi * 16 + g;    // token row
    int r1 = r0 + 8;
    int k0 = kb * 16 + 2 * q;

    float2 s01 = *(const float2*)(scales + k0);
    float2 s89 = *(const float2*)(scales + k0 + 8);

    float2 x00 = *(const float2*)(x + r0 * IN_F + k0);
    float2 x10 = *(const float2*)(x + r1 * IN_F + k0);
    float2 x08 = *(const float2*)(x + r0 * IN_F + k0 + 8);
    float2 x18 = *(const float2*)(x + r1 * IN_F + k0 + 8);

    __half2 h0 = __floats2half2_rn(x00.x * s01.x, x00.y * s01.y); // a0: row g,   k0..k0+1
    __half2 h1 = __floats2half2_rn(x10.x * s01.x, x10.y * s01.y); // a1: row g+8
    __half2 h2 = __floats2half2_rn(x08.x * s89.x, x08.y * s89.y); // a2: row g,   k0+8..+9
    __half2 h3 = __floats2half2_rn(x18.x * s89.x, x18.y * s89.y); // a3: row g+8

    uint4 v;
    v.x = *(const uint32_t*)&h0;
    v.y = *(const uint32_t*)&h1;
    v.z = *(const uint32_t*)&h2;
    v.w = *(const uint32_t*)&h3;
    g_xsfrag[(kb * 2 + mi) * 32 + lane] = v;
}

// ---------------------------------------------------------------------------
// GEMM: 448 CTAs x 128 threads. CTA owns 32 output features, warps split K.
// ---------------------------------------------------------------------------
__device__ __forceinline__ void mma16816(float c[4],
    uint32_t a0, uint32_t a1, uint32_t a2, uint32_t a3,
    uint32_t b0, uint32_t b1)
{
    asm volatile(
        "mma.sync.aligned.m16n8k16.row.col.f32.f16.f16.f32 "
        "{%0,%1,%2,%3}, {%4,%5,%6,%7}, {%8,%9}, {%0,%1,%2,%3};\n"
        : "+f"(c[0]), "+f"(c[1]), "+f"(c[2]), "+f"(c[3])
        : "r"(a0), "r"(a1), "r"(a2), "r"(a3), "r"(b0), "r"(b1));
}

__device__ __forceinline__ uint32_t pack_w_h2(int w0, int w1)
{
    __half2 h = __halves2half2(__int2half_rn(w0), __int2half_rn(w1));
    return *(const uint32_t*)&h;
}

__global__ __launch_bounds__(128) void gemm_q8_kernel(
    const int* __restrict__ W, float* __restrict__ out)
{
    const int lane = threadIdx.x & 31;
    const int warp = threadIdx.x >> 5;    // 0..3, splits K
    const int n0   = blockIdx.x * 32;     // output-feature tile base

    const int q = lane & 3;
    const int g = lane >> 2;

    // accumulators: [mi(2)][nfrag(4)][4]
    float c[2][4][4];
    #pragma unroll
    for (int a = 0; a < 2; a++)
        #pragma unroll
        for (int b = 0; b < 4; b++)
            #pragma unroll
            for (int d = 0; d < 4; d++) c[a][b][d] = 0.0f;

    const int kb0 = warp * 64;  // each warp: 64 k16-steps (K=1024)

    // weight base for this lane: row = n0 + g (+ j*8), col = 2*q (+ kb*16)
    const int* wrow = W + (size_t)(n0 + g) * IN_F + 2 * q;

    #pragma unroll 2
    for (int ks = 0; ks < 64; ks++) {
        const int kb = kb0 + ks;
        const int kofs = kb * 16;

        // A fragments (L2-resident, shared across all CTAs)
        uint4 A0 = g_xsfrag[(kb * 2 + 0) * 32 + lane];
        uint4 A1 = g_xsfrag[(kb * 2 + 1) * 32 + lane];

        // batch all 8 weight loads (int2 each) for MLP
        int2 wv0[4], wv1[4];
        #pragma unroll
        for (int j = 0; j < 4; j++) {
            const int* p = wrow + (size_t)j * 8 * IN_F + kofs;
            wv0[j] = *(const int2*)p;        // k = kofs+2q, +1
            wv1[j] = *(const int2*)(p + 8);  // k = kofs+2q+8, +9
        }

        #pragma unroll
        for (int j = 0; j < 4; j++) {
            uint32_t b0 = pack_w_h2(wv0[j].x, wv0[j].y);
            uint32_t b1 = pack_w_h2(wv1[j].x, wv1[j].y);
            mma16816(c[0][j], A0.x, A0.y, A0.z, A0.w, b0, b1);
            mma16816(c[1][j], A1.x, A1.y, A1.z, A1.w, b0, b1);
        }
    }

    // cross-warp K reduction through smem
    __shared__ float red[4][TOKENS][32];
    #pragma unroll
    for (int mi = 0; mi < 2; mi++) {
        #pragma unroll
        for (int j = 0; j < 4; j++) {
            int row = mi * 16 + g;
            int col = j * 8 + 2 * q;
            *(float2*)&red[warp][row][col]     = make_float2(c[mi][j][0], c[mi][j][1]);
            *(float2*)&red[warp][row + 8][col] = make_float2(c[mi][j][2], c[mi][j][3]);
        }
    }
    __syncthreads();

    const int col   = threadIdx.x & 31;
    const int rbase = (threadIdx.x >> 5) * 8;
    #pragma unroll
    for (int i = 0; i < 8; i++) {
        int row = rbase + i;
        float v = red[0][row][col] + red[1][row][col]
                + red[2][row][col] + red[3][row][col];
        out[(size_t)row * OUT_F + n0 + col] = v;
    }
}

// ---------------------------------------------------------------------------
extern "C" void kernel_launch(void* const* d_in, const int* in_sizes, int n_in,
                              void* d_out, int out_size)
{
    const float* x      = (const float*)d_in[0];
    const int*   weight = (const int*)d_in[1];
    const float* scales = (const float*)d_in[2];
    float*       out    = (float*)d_out;

    // 512 warps = 16384 threads for prep
    prep_xs_kernel<<<64, 256>>>(x, scales);
    // 14336/32 = 448 CTAs
    gemm_q8_kernel<<<448, 128>>>(weight, out);
}

// round 3
// speedup vs baseline: 1.4289x; 1.4289x over previous
#include <cuda_runtime.h>
#include <cuda_fp16.h>
#include <cstdint>

// out[32,14336] = (x * scales) @ W^T
//   x: [32,4096] f32, W: [14336,4096] int32 (|w|<=127), scales: [4096] f32
// HBM-bound: 235MB weight stream -> floor ~29us. m16n8k16 fp16 MMA hides compute.
// R2 change: 8 warps/CTA (256 thr) K-split to double resident warps (12->24/SM)
// and cover DRAM latency.

#define TOKENS 32
#define IN_F   4096
#define OUT_F  14336
#define NUM_KB (IN_F / 16)      // 256 k16-blocks

// A-fragments of xs=x*scales in fp16, fragment-major:
// index ((kb*2 + mi)*32 + lane) -> uint4 (8 fp16 = one m16k16 A frag slice)
__device__ uint4 g_xsfrag[NUM_KB * 2 * 32];

// ---------------------------------------------------------------------------
// Prep: build fragment-major fp16 xs. One warp per (kb, mi). 512 warps total.
// ---------------------------------------------------------------------------
__global__ __launch_bounds__(256) void prep_xs_kernel(
    const float* __restrict__ x, const float* __restrict__ scales)
{
    int wg   = blockIdx.x * (blockDim.x >> 5) + (threadIdx.x >> 5); // 0..511
    int lane = threadIdx.x & 31;
    int kb = wg >> 1;
    int mi = wg & 1;

    int q = lane & 3;        // k-quad
    int g = lane >> 2;       // group row
    int r0 = mi * 16 + g;    // token row
    int r1 = r0 + 8;
    int k0 = kb * 16 + 2 * q;

    float2 s01 = *(const float2*)(scales + k0);
    float2 s89 = *(const float2*)(scales + k0 + 8);

    float2 x00 = *(const float2*)(x + r0 * IN_F + k0);
    float2 x10 = *(const float2*)(x + r1 * IN_F + k0);
    float2 x08 = *(const float2*)(x + r0 * IN_F + k0 + 8);
    float2 x18 = *(const float2*)(x + r1 * IN_F + k0 + 8);

    __half2 h0 = __floats2half2_rn(x00.x * s01.x, x00.y * s01.y);
    __half2 h1 = __floats2half2_rn(x10.x * s01.x, x10.y * s01.y);
    __half2 h2 = __floats2half2_rn(x08.x * s89.x, x08.y * s89.y);
    __half2 h3 = __floats2half2_rn(x18.x * s89.x, x18.y * s89.y);

    uint4 v;
    v.x = *(const uint32_t*)&h0;
    v.y = *(const uint32_t*)&h1;
    v.z = *(const uint32_t*)&h2;
    v.w = *(const uint32_t*)&h3;
    g_xsfrag[(kb * 2 + mi) * 32 + lane] = v;
}

// ---------------------------------------------------------------------------
// GEMM: 448 CTAs x 256 threads. CTA owns 32 output features; 8 warps split K.
// ---------------------------------------------------------------------------
__device__ __forceinline__ void mma16816(float c[4],
    uint32_t a0, uint32_t a1, uint32_t a2, uint32_t a3,
    uint32_t b0, uint32_t b1)
{
    asm volatile(
        "mma.sync.aligned.m16n8k16.row.col.f32.f16.f16.f32 "
        "{%0,%1,%2,%3}, {%4,%5,%6,%7}, {%8,%9}, {%0,%1,%2,%3};\n"
        : "+f"(c[0]), "+f"(c[1]), "+f"(c[2]), "+f"(c[3])
        : "r"(a0), "r"(a1), "r"(a2), "r"(a3), "r"(b0), "r"(b1));
}

__device__ __forceinline__ uint32_t pack_w_h2(int w0, int w1)
{
    __half2 h = __halves2half2(__int2half_rn(w0), __int2half_rn(w1));
    return *(const uint32_t*)&h;
}

#define NWARPS 8
#define KSTEPS (NUM_KB / NWARPS)   // 32 k16-steps per warp

__global__ __launch_bounds__(256) void gemm_q8_kernel(
    const int* __restrict__ W, float* __restrict__ out)
{
    const int lane = threadIdx.x & 31;
    const int warp = threadIdx.x >> 5;    // 0..7, splits K
    const int n0   = blockIdx.x * 32;     // output-feature tile base

    const int q = lane & 3;
    const int g = lane >> 2;

    // accumulators: [mi(2)][nfrag(4)][4]
    float c[2][4][4];
    #pragma unroll
    for (int a = 0; a < 2; a++)
        #pragma unroll
        for (int b = 0; b < 4; b++)
            #pragma unroll
            for (int d = 0; d < 4; d++) c[a][b][d] = 0.0f;

    const int kb0 = warp * KSTEPS;

    // weight base for this lane: row = n0 + g (+ j*8), col = 2*q (+ kb*16)
    const int* wrow = W + (size_t)(n0 + g) * IN_F + 2 * q;

    #pragma unroll 2
    for (int ks = 0; ks < KSTEPS; ks++) {
        const int kb = kb0 + ks;
        const int kofs = kb * 16;

        // A fragments (L2-resident, shared across all CTAs)
        uint4 A0 = g_xsfrag[(kb * 2 + 0) * 32 + lane];
        uint4 A1 = g_xsfrag[(kb * 2 + 1) * 32 + lane];

        // batch all 8 weight loads (int2 each) for MLP
        int2 wv0[4], wv1[4];
        #pragma unroll
        for (int j = 0; j < 4; j++) {
            const int* p = wrow + (size_t)j * 8 * IN_F + kofs;
            wv0[j] = *(const int2*)p;        // k = kofs+2q, +1
            wv1[j] = *(const int2*)(p + 8);  // k = kofs+2q+8, +9
        }

        #pragma unroll
        for (int j = 0; j < 4; j++) {
            uint32_t b0 = pack_w_h2(wv0[j].x, wv0[j].y);
            uint32_t b1 = pack_w_h2(wv1[j].x, wv1[j].y);
            mma16816(c[0][j], A0.x, A0.y, A0.z, A0.w, b0, b1);
            mma16816(c[1][j], A1.x, A1.y, A1.z, A1.w, b0, b1);
        }
    }

    // cross-warp K reduction through smem (8 partials)
    __shared__ float red[NWARPS][TOKENS][32];
    #pragma unroll
    for (int mi = 0; mi < 2; mi++) {
        #pragma unroll
        for (int j = 0; j < 4; j++) {
            int row = mi * 16 + g;
            int col = j * 8 + 2 * q;
            *(float2*)&red[warp][row][col]     = make_float2(c[mi][j][0], c[mi][j][1]);
            *(float2*)&red[warp][row + 8][col] = make_float2(c[mi][j][2], c[mi][j][3]);
        }
    }
    __syncthreads();

    // 256 threads: each handles 4 (row,col) outputs
    const int col   = threadIdx.x & 31;
    const int rbase = (threadIdx.x >> 5) * 4;
    #pragma unroll
    for (int i = 0; i < 4; i++) {
        int row = rbase + i;
        float v = 0.0f;
        #pragma unroll
        for (int w = 0; w < NWARPS; w++) v += red[w][row][col];
        out[(size_t)row * OUT_F + n0 + col] = v;
    }
}

// ---------------------------------------------------------------------------
extern "C" void kernel_launch(void* const* d_in, const int* in_sizes, int n_in,
                              void* d_out, int out_size)
{
    const float* x      = (const float*)d_in[0];
    const int*   weight = (const int*)d_in[1];
    const float* scales = (const float*)d_in[2];
    float*       out    = (float*)d_out;

    prep_xs_kernel<<<64, 256>>>(x, scales);
    gemm_q8_kernel<<<448, 256>>>(weight, out);
}

// round 4
// speedup vs baseline: 1.5333x; 1.0731x over previous
#include <cuda_runtime.h>
#include <cuda_fp16.h>
#include <cstdint>

// out[32,14336] = (x * scales) @ W^T
//   x: [32,4096] f32, W: [14336,4096] int32 (|w|<=127), scales: [4096] f32
// HBM-bound: 235MB weight stream -> floor ~29us. m16n8k16 fp16 MMA hides compute.
// R3 change: explicit software pipeline (register double-buffer prefetch of W
// and A fragments) so loads stay continuously in flight; pin 3 CTAs/SM.

#define TOKENS 32
#define IN_F   4096
#define OUT_F  14336
#define NUM_KB (IN_F / 16)      // 256 k16-blocks

// A-fragments of xs=x*scales in fp16, fragment-major:
// index ((kb*2 + mi)*32 + lane) -> uint4 (8 fp16 = one m16k16 A frag slice)
__device__ uint4 g_xsfrag[NUM_KB * 2 * 32];

// ---------------------------------------------------------------------------
// Prep: build fragment-major fp16 xs. One warp per (kb, mi). 512 warps total.
// ---------------------------------------------------------------------------
__global__ __launch_bounds__(256) void prep_xs_kernel(
    const float* __restrict__ x, const float* __restrict__ scales)
{
    int wg   = blockIdx.x * (blockDim.x >> 5) + (threadIdx.x >> 5); // 0..511
    int lane = threadIdx.x & 31;
    int kb = wg >> 1;
    int mi = wg & 1;

    int q = lane & 3;        // k-quad
    int g = lane >> 2;       // group row
    int r0 = mi * 16 + g;    // token row
    int r1 = r0 + 8;
    int k0 = kb * 16 + 2 * q;

    float2 s01 = *(const float2*)(scales + k0);
    float2 s89 = *(const float2*)(scales + k0 + 8);

    float2 x00 = *(const float2*)(x + r0 * IN_F + k0);
    float2 x10 = *(const float2*)(x + r1 * IN_F + k0);
    float2 x08 = *(const float2*)(x + r0 * IN_F + k0 + 8);
    float2 x18 = *(const float2*)(x + r1 * IN_F + k0 + 8);

    __half2 h0 = __floats2half2_rn(x00.x * s01.x, x00.y * s01.y);
    __half2 h1 = __floats2half2_rn(x10.x * s01.x, x10.y * s01.y);
    __half2 h2 = __floats2half2_rn(x08.x * s89.x, x08.y * s89.y);
    __half2 h3 = __floats2half2_rn(x18.x * s89.x, x18.y * s89.y);

    uint4 v;
    v.x = *(const uint32_t*)&h0;
    v.y = *(const uint32_t*)&h1;
    v.z = *(const uint32_t*)&h2;
    v.w = *(const uint32_t*)&h3;
    g_xsfrag[(kb * 2 + mi) * 32 + lane] = v;
}

// ---------------------------------------------------------------------------
// GEMM: 448 CTAs x 256 threads. CTA owns 32 output features; 8 warps split K.
// ---------------------------------------------------------------------------
__device__ __forceinline__ void mma16816(float c[4],
    uint32_t a0, uint32_t a1, uint32_t a2, uint32_t a3,
    uint32_t b0, uint32_t b1)
{
    asm volatile(
        "mma.sync.aligned.m16n8k16.row.col.f32.f16.f16.f32 "
        "{%0,%1,%2,%3}, {%4,%5,%6,%7}, {%8,%9}, {%0,%1,%2,%3};\n"
        : "+f"(c[0]), "+f"(c[1]), "+f"(c[2]), "+f"(c[3])
        : "r"(a0), "r"(a1), "r"(a2), "r"(a3), "r"(b0), "r"(b1));
}

__device__ __forceinline__ uint32_t pack_w_h2(int w0, int w1)
{
    __half2 h = __halves2half2(__int2half_rn(w0), __int2half_rn(w1));
    return *(const uint32_t*)&h;
}

#define NWARPS 8
#define KSTEPS (NUM_KB / NWARPS)   // 32 k16-steps per warp

__global__ void __launch_bounds__(256, 3) gemm_q8_kernel(
    const int* __restrict__ W, float* __restrict__ out)
{
    const int lane = threadIdx.x & 31;
    const int warp = threadIdx.x >> 5;    // 0..7, splits K
    const int n0   = blockIdx.x * 32;     // output-feature tile base

    const int q = lane & 3;
    const int g = lane >> 2;

    // accumulators: [mi(2)][nfrag(4)][4]
    float c[2][4][4];
    #pragma unroll
    for (int a = 0; a < 2; a++)
        #pragma unroll
        for (int b = 0; b < 4; b++)
            #pragma unroll
            for (int d = 0; d < 4; d++) c[a][b][d] = 0.0f;

    const int kb0 = warp * KSTEPS;

    // weight base for this lane: row = n0 + g (+ j*8), col = 2*q (+ kb*16)
    const int* wrow = W + (size_t)(n0 + g) * IN_F + 2 * q;

    // ---- software pipeline: current buffers ----
    uint4 A0c, A1c;
    int2  wc0[4], wc1[4];
    {
        const int kofs = kb0 * 16;
        A0c = g_xsfrag[(kb0 * 2 + 0) * 32 + lane];
        A1c = g_xsfrag[(kb0 * 2 + 1) * 32 + lane];
        #pragma unroll
        for (int j = 0; j < 4; j++) {
            const int* p = wrow + (size_t)j * 8 * IN_F + kofs;
            wc0[j] = *(const int2*)p;
            wc1[j] = *(const int2*)(p + 8);
        }
    }

    #pragma unroll 2
    for (int ks = 0; ks < KSTEPS; ks++) {
        // prefetch next iteration (clamped on the last iter -> L1-hit reload)
        const int ksn  = (ks + 1 < KSTEPS) ? (ks + 1) : ks;
        const int kbn  = kb0 + ksn;
        const int kofn = kbn * 16;

        uint4 A0n = g_xsfrag[(kbn * 2 + 0) * 32 + lane];
        uint4 A1n = g_xsfrag[(kbn * 2 + 1) * 32 + lane];
        int2  wn0[4], wn1[4];
        #pragma unroll
        for (int j = 0; j < 4; j++) {
            const int* p = wrow + (size_t)j * 8 * IN_F + kofn;
            wn0[j] = *(const int2*)p;
            wn1[j] = *(const int2*)(p + 8);
        }

        // compute on current buffers (loads already resolved one iter ago)
        #pragma unroll
        for (int j = 0; j < 4; j++) {
            uint32_t b0 = pack_w_h2(wc0[j].x, wc0[j].y);
            uint32_t b1 = pack_w_h2(wc1[j].x, wc1[j].y);
            mma16816(c[0][j], A0c.x, A0c.y, A0c.z, A0c.w, b0, b1);
            mma16816(c[1][j], A1c.x, A1c.y, A1c.z, A1c.w, b0, b1);
        }

        // rotate buffers (register moves; eliminated by unroll-2)
        A0c = A0n; A1c = A1n;
        #pragma unroll
        for (int j = 0; j < 4; j++) { wc0[j] = wn0[j]; wc1[j] = wn1[j]; }
    }

    // cross-warp K reduction through smem (8 partials)
    __shared__ float red[NWARPS][TOKENS][32];
    #pragma unroll
    for (int mi = 0; mi < 2; mi++) {
        #pragma unroll
        for (int j = 0; j < 4; j++) {
            int row = mi * 16 + g;
            int col = j * 8 + 2 * q;
            *(float2*)&red[warp][row][col]     = make_float2(c[mi][j][0], c[mi][j][1]);
            *(float2*)&red[warp][row + 8][col] = make_float2(c[mi][j][2], c[mi][j][3]);
        }
    }
    __syncthreads();

    // 256 threads: each handles 4 (row,col) outputs
    const int col   = threadIdx.x & 31;
    const int rbase = (threadIdx.x >> 5) * 4;
    #pragma unroll
    for (int i = 0; i < 4; i++) {
        int row = rbase + i;
        float v = 0.0f;
        #pragma unroll
        for (int w = 0; w < NWARPS; w++) v += red[w][row][col];
        out[(size_t)row * OUT_F + n0 + col] = v;
    }
}

// ---------------------------------------------------------------------------
extern "C" void kernel_launch(void* const* d_in, const int* in_sizes, int n_in,
                              void* d_out, int out_size)
{
    const float* x      = (const float*)d_in[0];
    const int*   weight = (const int*)d_in[1];
    const float* scales = (const float*)d_in[2];
    float*       out    = (float*)d_out;

    prep_xs_kernel<<<64, 256>>>(x, scales);
    gemm_q8_kernel<<<448, 256>>>(weight, out);
}

// round 6
// speedup vs baseline: 1.6716x; 1.0901x over previous
#include <cuda_runtime.h>
#include <cuda_fp16.h>
#include <cstdint>

// out[32,14336] = (x * scales) @ W^T
//   x: [32,4096] f32, W: [14336,4096] int32 (|w|<=127), scales: [4096] f32
// HBM-bound: 235MB weight stream -> floor ~29us.
// R4 change: permuted k-layout so each lane's 4 B-fragment k-values are one
// contiguous int4 -> LDG.128 weight loads, halving L1tex wavefronts (the R3
// bottleneck: L1=68% > DRAM=64%).
//
// k-permutation (per k16 block): lane quad q owns physical k = kb*16+4q..+3,
// mapped to fragment positions b0=(2q,2q+1), b1=(2q+8,2q+9). A fragments are
// built with the SAME mapping by prep, so the GEMM is unchanged semantically.

#define TOKENS 32
#define IN_F   4096
#define OUT_F  14336
#define NUM_KB (IN_F / 16)      // 256 k16-blocks

// A-fragments of xs=x*scales in fp16, fragment-major:
// index ((kb*2 + mi)*32 + lane) -> uint4 (8 fp16 = one m16k16 A frag slice)
__device__ uint4 g_xsfrag[NUM_KB * 2 * 32];

// ---------------------------------------------------------------------------
// Prep: build fragment-major fp16 xs with the permuted k-layout.
// One warp per (kb, mi). 512 warps total. float4-coalesced x loads.
// ---------------------------------------------------------------------------
__global__ __launch_bounds__(256) void prep_xs_kernel(
    const float* __restrict__ x, const float* __restrict__ scales)
{
    int wg   = blockIdx.x * (blockDim.x >> 5) + (threadIdx.x >> 5); // 0..511
    int lane = threadIdx.x & 31;
    int kb = wg >> 1;
    int mi = wg & 1;

    int q = lane & 3;        // k-quad
    int g = lane >> 2;       // group row
    int r0 = mi * 16 + g;    // token row
    int r1 = r0 + 8;
    int k0 = kb * 16 + 4 * q;   // physical k base for this lane (contiguous 4)

    float4 s  = *(const float4*)(scales + k0);
    float4 x0 = *(const float4*)(x + r0 * IN_F + k0);
    float4 x1 = *(const float4*)(x + r1 * IN_F + k0);

    // fragment regs: a0/a1 = k-pair (4q,4q+1) rows r0/r1; a2/a3 = (4q+2,4q+3)
    __half2 h0 = __floats2half2_rn(x0.x * s.x, x0.y * s.y);
    __half2 h1 = __floats2half2_rn(x1.x * s.x, x1.y * s.y);
    __half2 h2 = __floats2half2_rn(x0.z * s.z, x0.w * s.w);
    __half2 h3 = __floats2half2_rn(x1.z * s.z, x1.w * s.w);

    uint4 v;
    v.x = *(const uint32_t*)&h0;
    v.y = *(const uint32_t*)&h1;
    v.z = *(const uint32_t*)&h2;
    v.w = *(const uint32_t*)&h3;
    g_xsfrag[(kb * 2 + mi) * 32 + lane] = v;
}

// ---------------------------------------------------------------------------
// GEMM: 448 CTAs x 256 threads. CTA owns 32 output features; 8 warps split K.
// ---------------------------------------------------------------------------
__device__ __forceinline__ void mma16816(float c[4],
    uint32_t a0, uint32_t a1, uint32_t a2, uint32_t a3,
    uint32_t b0, uint32_t b1)
{
    asm volatile(
        "mma.sync.aligned.m16n8k16.row.col.f32.f16.f16.f32 "
        "{%0,%1,%2,%3}, {%4,%5,%6,%7}, {%8,%9}, {%0,%1,%2,%3};\n"
        : "+f"(c[0]), "+f"(c[1]), "+f"(c[2]), "+f"(c[3])
        : "r"(a0), "r"(a1), "r"(a2), "r"(a3), "r"(b0), "r"(b1));
}

__device__ __forceinline__ uint32_t pack_w_h2(int w0, int w1)
{
    __half2 h = __halves2half2(__int2half_rn(w0), __int2half_rn(w1));
    return *(const uint32_t*)&h;
}

#define NWARPS 8
#define KSTEPS (NUM_KB / NWARPS)   // 32 k16-steps per warp

__global__ void __launch_bounds__(256, 3) gemm_q8_kernel(
    const int* __restrict__ W, float* __restrict__ out)
{
    const int lane = threadIdx.x & 31;
    const int warp = threadIdx.x >> 5;    // 0..7, splits K
    const int n0   = blockIdx.x * 32;     // output-feature tile base

    const int q = lane & 3;
    const int g = lane >> 2;

    // accumulators: [mi(2)][nfrag(4)][4]
    float c[2][4][4];
    #pragma unroll
    for (int a = 0; a < 2; a++)
        #pragma unroll
        for (int b = 0; b < 4; b++)
            #pragma unroll
            for (int d = 0; d < 4; d++) c[a][b][d] = 0.0f;

    const int kb0 = warp * KSTEPS;

    // weight base: row = n0 + g (+ j*8), col = 4q (+ kb*16) -- one int4/lane
    const int* wrow = W + (size_t)(n0 + g) * IN_F + 4 * q;

    // ---- software pipeline: current buffers ----
    uint4 A0c, A1c;
    int4  wc[4];
    {
        const int kofs = kb0 * 16;
        A0c = g_xsfrag[(kb0 * 2 + 0) * 32 + lane];
        A1c = g_xsfrag[(kb0 * 2 + 1) * 32 + lane];
        #pragma unroll
        for (int j = 0; j < 4; j++)
            wc[j] = *(const int4*)(wrow + (size_t)j * 8 * IN_F + kofs);
    }

    #pragma unroll 2
    for (int ks = 0; ks < KSTEPS; ks++) {
        // prefetch next iteration (clamped on last iter -> L1-hit reload)
        const int ksn  = (ks + 1 < KSTEPS) ? (ks + 1) : ks;
        const int kbn  = kb0 + ksn;
        const int kofn = kbn * 16;

        uint4 A0n = g_xsfrag[(kbn * 2 + 0) * 32 + lane];
        uint4 A1n = g_xsfrag[(kbn * 2 + 1) * 32 + lane];
        int4  wn[4];
        #pragma unroll
        for (int j = 0; j < 4; j++)
            wn[j] = *(const int4*)(wrow + (size_t)j * 8 * IN_F + kofn);

        // compute on current buffers
        #pragma unroll
        for (int j = 0; j < 4; j++) {
            uint32_t b0 = pack_w_h2(wc[j].x, wc[j].y);
            uint32_t b1 = pack_w_h2(wc[j].z, wc[j].w);
            mma16816(c[0][j], A0c.x, A0c.y, A0c.z, A0c.w, b0, b1);
            mma16816(c[1][j], A1c.x, A1c.y, A1c.z, A1c.w, b0, b1);
        }

        // rotate buffers
        A0c = A0n; A1c = A1n;
        #pragma unroll
        for (int j = 0; j < 4; j++) wc[j] = wn[j];
    }

    // cross-warp K reduction through smem (8 partials).
    // NOTE: fragment column positions (2q,2q+1 / 2q+8,2q+9) are LOGICAL n
    // columns -- the n-dimension is NOT permuted, only k was. c[mi][j][0..1]
    // are rows (mi*16+g, +8) x cols (j*8+2q, +1); [2..3] same cols rows +8.
    __shared__ float red[NWARPS][TOKENS][32];
    #pragma unroll
    for (int mi = 0; mi < 2; mi++) {
        #pragma unroll
        for (int j = 0; j < 4; j++) {
            int row = mi * 16 + g;
            int col = j * 8 + 2 * q;
            *(float2*)&red[warp][row][col]     = make_float2(c[mi][j][0], c[mi][j][1]);
            *(float2*)&red[warp][row + 8][col] = make_float2(c[mi][j][2], c[mi][j][3]);
        }
    }
    __syncthreads();

    // 256 threads: each handles 4 (row,col) outputs
    const int col   = threadIdx.x & 31;
    const int rbase = (threadIdx.x >> 5) * 4;
    #pragma unroll
    for (int i = 0; i < 4; i++) {
        int row = rbase + i;
        float v = 0.0f;
        #pragma unroll
        for (int w = 0; w < NWARPS; w++) v += red[w][row][col];
        out[(size_t)row * OUT_F + n0 + col] = v;
    }
}

// ---------------------------------------------------------------------------
extern "C" void kernel_launch(void* const* d_in, const int* in_sizes, int n_in,
                              void* d_out, int out_size)
{
    const float* x      = (const float*)d_in[0];
    const int*   weight = (const int*)d_in[1];
    const float* scales = (const float*)d_in[2];
    float*       out    = (float*)d_out;

    prep_xs_kernel<<<64, 256>>>(x, scales);
    gemm_q8_kernel<<<448, 256>>>(weight, out);
}